// round 3
// baseline (speedup 1.0000x reference)
#include <cuda_runtime.h>
#include <cuda_bf16.h>

#define NN 256
#define KK 64
#define TT 128
#define FF 64

// ---------------- scratch (no allocations allowed) ----------------
__device__ float g_x2[NN * FF];     // sum over t of x^2, per (n,f)
__device__ float g_c2[KK * FF];     // sum over t of c^2, per (k,f)
__device__ float g_dist[NN * KK];   // distance matrix
__device__ float g_q[NN * KK];      // softmax q
__device__ float g_qsum[KK];        // column sums of q
__device__ float g_lossp[NN];       // per-row partial loss

__device__ __forceinline__ float fsqrt_approx(float x) {
    float r;
    asm("sqrt.approx.f32 %0, %1;" : "=f"(r) : "f"(x));
    return r;
}

// ---------------- kernel 1: x2 / c2 ----------------
// grid = NN + KK blocks, 64 threads (one per f)
__global__ void sq_kernel(const float* __restrict__ x, const float* __restrict__ c) {
    int b = blockIdx.x;
    int f = threadIdx.x;
    const float* src;
    float* dst;
    if (b < NN) { src = x + (size_t)b * TT * FF; dst = g_x2 + b * FF; }
    else        { src = c + (size_t)(b - NN) * TT * FF; dst = g_c2 + (b - NN) * FF; }
    float s = 0.0f;
#pragma unroll 8
    for (int t = 0; t < TT; t++) {
        float v = src[t * FF + f];
        s = fmaf(v, v, s);
    }
    dst[f] = s;
}

// ---------------- kernel 2: distance ----------------
// Tile: TN=8 n-rows x TK=16 k-rows, T chunked by TC=8.
// 128 threads: fg = tid&15 (f-group of 4 floats), pg = tid>>4:
//   ni = pg&1 (2 n-subtiles of 4), ki = pg>>1 (4 k-subtiles of 4)
// Each thread: 4x4 (n,k) outer product over 4 f's -> 64-float accumulator.
#define TN 8
#define TK 16
#define TC 8

__global__ void __launch_bounds__(128, 4)
dist_kernel(const float* __restrict__ x, const float* __restrict__ c) {
    __shared__ float4 xs4[TN * TC * (FF / 4)];   // [nn][tt][f4] 16KB
    __shared__ float4 cs4[TK * TC * (FF / 4)];   // [kk][tt][f4] 32KB

    const int tid = threadIdx.x;
    const int fg  = tid & 15;
    const int pg  = tid >> 4;
    const int ni  = pg & 1;
    const int ki  = pg >> 1;
    const int n0  = blockIdx.y * TN;
    const int k0  = blockIdx.x * TK;

    const float4* __restrict__ xg = (const float4*)x;   // index: (n*TT + t)*16 + f4
    const float4* __restrict__ cg = (const float4*)c;

    float4 acc[4][4];
#pragma unroll
    for (int i = 0; i < 4; i++)
#pragma unroll
        for (int j = 0; j < 4; j++)
            acc[i][j] = make_float4(0.f, 0.f, 0.f, 0.f);

    for (int t0 = 0; t0 < TT; t0 += TC) {
        __syncthreads();
        // load x tile: 8*8*16 = 1024 float4, 8 per thread
#pragma unroll
        for (int i = 0; i < 8; i++) {
            int idx   = tid + i * 128;
            int nn    = idx >> 7;          // /128
            int inner = idx & 127;         // tt*16 + f4
            xs4[idx] = xg[((n0 + nn) * TT + t0 + (inner >> 4)) * 16 + (inner & 15)];
        }
        // load c tile: 16*8*16 = 2048 float4, 16 per thread
#pragma unroll
        for (int i = 0; i < 16; i++) {
            int idx   = tid + i * 128;
            int kk    = idx >> 7;
            int inner = idx & 127;
            cs4[idx] = cg[((k0 + kk) * TT + t0 + (inner >> 4)) * 16 + (inner & 15)];
        }
        __syncthreads();

#pragma unroll
        for (int tt = 0; tt < TC; tt++) {
            float4 xv[4], cv[4];
#pragma unroll
            for (int i = 0; i < 4; i++)
                xv[i] = xs4[((ni * 4 + i) * TC + tt) * 16 + fg];
#pragma unroll
            for (int j = 0; j < 4; j++)
                cv[j] = cs4[((ki * 4 + j) * TC + tt) * 16 + fg];
#pragma unroll
            for (int i = 0; i < 4; i++)
#pragma unroll
                for (int j = 0; j < 4; j++) {
                    acc[i][j].x = fmaf(xv[i].x, cv[j].x, acc[i][j].x);
                    acc[i][j].y = fmaf(xv[i].y, cv[j].y, acc[i][j].y);
                    acc[i][j].z = fmaf(xv[i].z, cv[j].z, acc[i][j].z);
                    acc[i][j].w = fmaf(xv[i].w, cv[j].w, acc[i][j].w);
                }
        }
    }

    // epilogue: d2 = max(x2 + c2 - 2*xc, 0); partial dist = sum_f sqrt(d2)
    const float4* __restrict__ x2g = (const float4*)g_x2;   // [n][f4]: n*16+f4
    const float4* __restrict__ c2g = (const float4*)g_c2;
    float4 x2v[4], c2v[4];
#pragma unroll
    for (int i = 0; i < 4; i++) x2v[i] = x2g[(n0 + ni * 4 + i) * 16 + fg];
#pragma unroll
    for (int j = 0; j < 4; j++) c2v[j] = c2g[(k0 + ki * 4 + j) * 16 + fg];

#pragma unroll
    for (int i = 0; i < 4; i++) {
#pragma unroll
        for (int j = 0; j < 4; j++) {
            float4 a = acc[i][j];
            float dx = fmaxf(x2v[i].x + c2v[j].x - 2.0f * a.x, 0.0f);
            float dy = fmaxf(x2v[i].y + c2v[j].y - 2.0f * a.y, 0.0f);
            float dz = fmaxf(x2v[i].z + c2v[j].z - 2.0f * a.z, 0.0f);
            float dw = fmaxf(x2v[i].w + c2v[j].w - 2.0f * a.w, 0.0f);
            float part = fsqrt_approx(dx) + fsqrt_approx(dy) +
                         fsqrt_approx(dz) + fsqrt_approx(dw);
            // reduce over the 16 fg lanes (contiguous within half-warp)
#pragma unroll
            for (int off = 8; off; off >>= 1)
                part += __shfl_down_sync(0xffffffffu, part, off, 16);
            if (fg == 0)
                g_dist[(n0 + ni * 4 + i) * KK + (k0 + ki * 4 + j)] = part;
        }
    }
}

// ---------------- kernel 3: q = softmax_k( 1/(1+d^2) ) ----------------
// alpha=1 -> exponent (alpha+1)/2 = 1, so q_pre = 1/(1+d^2)
__global__ void q_kernel() {
    int n = blockIdx.x;
    int k = threadIdx.x;           // 64 threads = 2 warps
    float d  = g_dist[n * KK + k];
    float q1 = 1.0f / (1.0f + d * d);

    __shared__ float red[2];
    float m = q1;
#pragma unroll
    for (int o = 16; o; o >>= 1) m = fmaxf(m, __shfl_xor_sync(0xffffffffu, m, o));
    if ((k & 31) == 0) red[k >> 5] = m;
    __syncthreads();
    m = fmaxf(red[0], red[1]);
    __syncthreads();

    float e = expf(q1 - m);
    float s = e;
#pragma unroll
    for (int o = 16; o; o >>= 1) s += __shfl_xor_sync(0xffffffffu, s, o);
    if ((k & 31) == 0) red[k >> 5] = s;
    __syncthreads();
    s = red[0] + red[1];

    g_q[n * KK + k] = e / s;
}

// ---------------- kernel 4: qsum[k] = sum_n q[n][k] (deterministic) ----------------
__global__ void qsum_kernel() {
    int k = threadIdx.x;   // 64 threads
    float s = 0.0f;
#pragma unroll 8
    for (int n = 0; n < NN; n++) s += g_q[n * KK + k];
    g_qsum[k] = s;
}

// ---------------- kernel 5: p = softmax_k(q^2/qsum); per-row loss partial ----------------
__global__ void p_loss_kernel() {
    int n = blockIdx.x;
    int k = threadIdx.x;
    float q = g_q[n * KK + k];
    float t = (q * q) / g_qsum[k];

    __shared__ float red[2];
    float m = t;
#pragma unroll
    for (int o = 16; o; o >>= 1) m = fmaxf(m, __shfl_xor_sync(0xffffffffu, m, o));
    if ((k & 31) == 0) red[k >> 5] = m;
    __syncthreads();
    m = fmaxf(red[0], red[1]);
    __syncthreads();

    float e = expf(t - m);
    float s = e;
#pragma unroll
    for (int o = 16; o; o >>= 1) s += __shfl_xor_sync(0xffffffffu, s, o);
    if ((k & 31) == 0) red[k >> 5] = s;
    __syncthreads();
    s = red[0] + red[1];
    float p = e / s;

    // loss term: q * (log(q) - p)
    float term = q * (logf(q) - p);
#pragma unroll
    for (int o = 16; o; o >>= 1) term += __shfl_xor_sync(0xffffffffu, term, o);
    __syncthreads();
    if ((k & 31) == 0) red[k >> 5] = term;
    __syncthreads();
    if (k == 0) g_lossp[n] = red[0] + red[1];
}

// ---------------- kernel 6: finalize output ----------------
// blocks 0..63 copy q (16384 floats); block 64 reduces loss (256 values)
__global__ void finalize_kernel(float* __restrict__ out, int out_size) {
    if (blockIdx.x < 64) {
        int idx = blockIdx.x * 256 + threadIdx.x;
        if (idx < out_size) out[idx] = g_q[idx];
    } else {
        __shared__ float sm[256];
        int tid = threadIdx.x;
        sm[tid] = g_lossp[tid];
        __syncthreads();
#pragma unroll
        for (int o = 128; o; o >>= 1) {
            if (tid < o) sm[tid] += sm[tid + o];
            __syncthreads();
        }
        if (tid == 0 && out_size > NN * KK)
            out[NN * KK] = sm[0] / (float)NN;
    }
}

extern "C" void kernel_launch(void* const* d_in, const int* in_sizes, int n_in,
                              void* d_out, int out_size) {
    const float* x = (const float*)d_in[0];   // inputs  (N,T,F)
    const float* c = (const float*)d_in[1];   // clusters(K,T,F)
    float* out = (float*)d_out;

    sq_kernel<<<NN + KK, 64>>>(x, c);
    dim3 dgrid(KK / TK, NN / TN);             // (4, 32)
    dist_kernel<<<dgrid, 128>>>(x, c);
    q_kernel<<<NN, 64>>>();
    qsum_kernel<<<1, 64>>>();
    p_loss_kernel<<<NN, 64>>>();
    finalize_kernel<<<65, 256>>>(out, out_size);
}

// round 7
// speedup vs baseline: 1.5885x; 1.5885x over previous
#include <cuda_runtime.h>

#define NN 256
#define KK 64
#define TT 128
#define FF 64
#define TN 8
#define TK 16
#define TC 8
#define GRID 128

typedef unsigned long long u64;

// ---------------- scratch (no allocations allowed) ----------------
__device__ float g_dist[NN * KK];
__device__ float g_q[NN * KK];
__device__ float g_qpart[GRID * KK];   // per-block 2-row column partials
__device__ float g_lossb[GRID];        // per-block loss partials
__device__ int g_c1, g_f1, g_c2, g_f2, g_c3;   // sync counters/flags (zero-init)

__device__ __forceinline__ u64 ffma2(u64 a, u64 b, u64 c) {
    u64 d;
    asm("fma.rn.f32x2 %0, %1, %2, %3;" : "=l"(d) : "l"(a), "l"(b), "l"(c));
    return d;
}
__device__ __forceinline__ float2 upk(u64 v) {
    float2 r;
    asm("mov.b64 {%0, %1}, %2;" : "=f"(r.x), "=f"(r.y) : "l"(v));
    return r;
}
__device__ __forceinline__ float fsqrt_approx(float x) {
    float r;
    asm("sqrt.approx.f32 %0, %1;" : "=f"(r) : "f"(x));
    return r;
}

// device-wide barrier: all GRID blocks co-resident (128 <= 148 SMs)
__device__ __forceinline__ void gsync(int* cnt, int* flag) {
    __syncthreads();
    if (threadIdx.x == 0) {
        __threadfence();
        if (atomicAdd(cnt, 1) == GRID - 1) {
            atomicExch(flag, 1);
        } else {
            while (atomicAdd(flag, 0) == 0) { __nanosleep(64); }
        }
    }
    __syncthreads();
}

__global__ void __launch_bounds__(128, 1)
soft_kmeans_mega(const float* __restrict__ x, const float* __restrict__ c,
                 float* __restrict__ out, int out_size) {
    // 48KB tiles; softmax-phase smem aliases xs4 after phase 1.
    __shared__ float4 xs4[TN * TC * (FF / 4)];   // 16KB
    __shared__ float4 cs4[TK * TC * (FF / 4)];   // 32KB

    const int tid = threadIdx.x;
    const int b   = blockIdx.x;

    // ================= Phase 1: distance tile (8n x 16k) =================
    {
        const int fg = tid & 15;        // f-group of 4 floats
        const int pg = tid >> 4;
        const int ni = pg & 1;          // 2 n-subtiles of 4
        const int ki = pg >> 1;         // 4 k-subtiles of 4
        const int kt = b & 3;
        const int nt = b >> 2;
        const int n0 = nt * TN;
        const int k0 = kt * TK;

        const float4* __restrict__ xg = (const float4*)x;  // (n*TT + t)*16 + f4
        const float4* __restrict__ cg = (const float4*)c;

        u64 acc[4][4][2];
        u64 x2a[4][2], c2a[4][2];
#pragma unroll
        for (int i = 0; i < 4; i++) {
            x2a[i][0] = 0ull; x2a[i][1] = 0ull;
            c2a[i][0] = 0ull; c2a[i][1] = 0ull;
#pragma unroll
            for (int j = 0; j < 4; j++) { acc[i][j][0] = 0ull; acc[i][j][1] = 0ull; }
        }

        const ulonglong2* xsu = reinterpret_cast<const ulonglong2*>(xs4);
        const ulonglong2* csu = reinterpret_cast<const ulonglong2*>(cs4);

        for (int t0 = 0; t0 < TT; t0 += TC) {
            __syncthreads();
            // x tile: 8*8*16 = 1024 float4, 8 per thread
#pragma unroll
            for (int i = 0; i < 8; i++) {
                int idx   = tid + i * 128;
                int nn    = idx >> 7;
                int inner = idx & 127;            // tt*16 + f4
                xs4[idx] = xg[((n0 + nn) * TT + t0 + (inner >> 4)) * 16 + (inner & 15)];
            }
            // c tile: 16*8*16 = 2048 float4, 16 per thread
#pragma unroll
            for (int i = 0; i < 16; i++) {
                int idx   = tid + i * 128;
                int kk    = idx >> 7;
                int inner = idx & 127;
                cs4[idx] = cg[((k0 + kk) * TT + t0 + (inner >> 4)) * 16 + (inner & 15)];
            }
            __syncthreads();

#pragma unroll
            for (int tt = 0; tt < TC; tt++) {
                ulonglong2 xv[4], cv[4];
#pragma unroll
                for (int i = 0; i < 4; i++)
                    xv[i] = xsu[((ni * 4 + i) * TC + tt) * 16 + fg];
#pragma unroll
                for (int j = 0; j < 4; j++)
                    cv[j] = csu[((ki * 4 + j) * TC + tt) * 16 + fg];
                // fused x^2 / c^2 accumulation (replaces sq_kernel)
#pragma unroll
                for (int i = 0; i < 4; i++) {
                    x2a[i][0] = ffma2(xv[i].x, xv[i].x, x2a[i][0]);
                    x2a[i][1] = ffma2(xv[i].y, xv[i].y, x2a[i][1]);
                }
#pragma unroll
                for (int j = 0; j < 4; j++) {
                    c2a[j][0] = ffma2(cv[j].x, cv[j].x, c2a[j][0]);
                    c2a[j][1] = ffma2(cv[j].y, cv[j].y, c2a[j][1]);
                }
#pragma unroll
                for (int i = 0; i < 4; i++)
#pragma unroll
                    for (int j = 0; j < 4; j++) {
                        acc[i][j][0] = ffma2(xv[i].x, cv[j].x, acc[i][j][0]);
                        acc[i][j][1] = ffma2(xv[i].y, cv[j].y, acc[i][j][1]);
                    }
            }
        }

        // epilogue: d2 = max(x2 + c2 - 2*xc, 0); dist += sqrt(d2) over f
#pragma unroll
        for (int i = 0; i < 4; i++) {
            float2 xa0 = upk(x2a[i][0]), xa1 = upk(x2a[i][1]);
#pragma unroll
            for (int j = 0; j < 4; j++) {
                float2 ca0 = upk(c2a[j][0]), ca1 = upk(c2a[j][1]);
                float2 a0 = upk(acc[i][j][0]), a1 = upk(acc[i][j][1]);
                float d0 = fmaxf(xa0.x + ca0.x - 2.0f * a0.x, 0.0f);
                float d1 = fmaxf(xa0.y + ca0.y - 2.0f * a0.y, 0.0f);
                float d2 = fmaxf(xa1.x + ca1.x - 2.0f * a1.x, 0.0f);
                float d3 = fmaxf(xa1.y + ca1.y - 2.0f * a1.y, 0.0f);
                float part = fsqrt_approx(d0) + fsqrt_approx(d1) +
                             fsqrt_approx(d2) + fsqrt_approx(d3);
#pragma unroll
                for (int off = 8; off; off >>= 1)
                    part += __shfl_down_sync(0xffffffffu, part, off, 16);
                if (fg == 0)
                    g_dist[(n0 + ni * 4 + i) * KK + (k0 + ki * 4 + j)] = part;
            }
        }
    }

    gsync(&g_c1, &g_f1);   // g_dist complete everywhere

    // smem aliases for softmax phases (tiles dead now)
    float* s_tmp  = (float*)xs4;          // 128 floats
    float* s_red  = (float*)xs4 + 128;    // 4 floats
    int*   s_last = (int*)((float*)xs4 + 136);

    // ================= Phase 2: q = softmax_k(1/(1+d^2)), rows 2b, 2b+1 ====
    const int rloc = tid >> 6;            // 0..1 : which of the block's 2 rows
    const int k    = tid & 63;
    const int n    = b * 2 + rloc;
    const int w    = tid >> 5;            // warp id 0..3
    const int lane = tid & 31;

    float q;
    {
        float d  = g_dist[n * KK + k];
        float q1 = 1.0f / (1.0f + d * d);       // alpha=1 -> exponent 1

        float m = q1;
#pragma unroll
        for (int o = 16; o; o >>= 1) m = fmaxf(m, __shfl_xor_sync(0xffffffffu, m, o));
        if (lane == 0) s_red[w] = m;
        __syncthreads();
        m = fmaxf(s_red[rloc * 2], s_red[rloc * 2 + 1]);
        __syncthreads();

        float e = expf(q1 - m);
        float s = e;
#pragma unroll
        for (int o = 16; o; o >>= 1) s += __shfl_xor_sync(0xffffffffu, s, o);
        if (lane == 0) s_red[w] = s;
        __syncthreads();
        s = s_red[rloc * 2] + s_red[rloc * 2 + 1];
        __syncthreads();

        q = e / s;
        g_q[n * KK + k] = q;
        out[n * KK + k] = q;

        // block column partial: q(row0,k) + q(row1,k)
        s_tmp[tid] = q;
        __syncthreads();
        if (tid < 64) g_qpart[b * KK + tid] = s_tmp[tid] + s_tmp[tid + 64];
        __syncthreads();
    }

    gsync(&g_c2, &g_f2);   // all qpart written

    // ================= Phase 3: qsum, p, loss =================
    {
        // qsum[k] = sum over 128 blocks of g_qpart[bb][k]; split across rloc halves
        float part = 0.0f;
        const int b0 = rloc * 64;
#pragma unroll 8
        for (int bb = 0; bb < 64; bb++) part += g_qpart[(b0 + bb) * KK + k];
        s_tmp[tid] = part;
        __syncthreads();
        float qsum = s_tmp[k] + s_tmp[64 + k];
        __syncthreads();

        float t = (q * q) / qsum;

        float m = t;
#pragma unroll
        for (int o = 16; o; o >>= 1) m = fmaxf(m, __shfl_xor_sync(0xffffffffu, m, o));
        if (lane == 0) s_red[w] = m;
        __syncthreads();
        m = fmaxf(s_red[rloc * 2], s_red[rloc * 2 + 1]);
        __syncthreads();

        float e = expf(t - m);
        float s = e;
#pragma unroll
        for (int o = 16; o; o >>= 1) s += __shfl_xor_sync(0xffffffffu, s, o);
        if (lane == 0) s_red[w] = s;
        __syncthreads();
        s = s_red[rloc * 2] + s_red[rloc * 2 + 1];
        __syncthreads();

        float p = e / s;

        float term = q * (logf(q) - p);
#pragma unroll
        for (int o = 16; o; o >>= 1) term += __shfl_xor_sync(0xffffffffu, term, o);
        if (lane == 0) s_red[w] = term;
        __syncthreads();
        if (tid == 0)   // both rows' warps sum = block total
            g_lossb[b] = s_red[0] + s_red[1] + s_red[2] + s_red[3];
        __syncthreads();
    }

    // ================= Phase 4: last block finalizes loss, resets sync =====
    if (tid == 0) {
        __threadfence();
        int old = atomicAdd(&g_c3, 1);
        *s_last = (old == GRID - 1) ? 1 : 0;
    }
    __syncthreads();
    if (*s_last) {
        s_tmp[tid] = g_lossb[tid];       // 128 threads, 128 values
        __syncthreads();
#pragma unroll
        for (int o = 64; o; o >>= 1) {
            if (tid < o) s_tmp[tid] += s_tmp[tid + o];
            __syncthreads();
        }
        if (tid == 0) {
            if (out_size > NN * KK) out[NN * KK] = s_tmp[0] / (float)NN;
            // reset for next graph replay (all blocks already past all waits)
            atomicExch(&g_c1, 0); atomicExch(&g_f1, 0);
            atomicExch(&g_c2, 0); atomicExch(&g_f2, 0);
            atomicExch(&g_c3, 0);
            __threadfence();
        }
    }
}

extern "C" void kernel_launch(void* const* d_in, const int* in_sizes, int n_in,
                              void* d_out, int out_size) {
    const float* x = (const float*)d_in[0];   // inputs  (N,T,F)
    const float* c = (const float*)d_in[1];   // clusters(K,T,F)
    float* out = (float*)d_out;

    soft_kmeans_mega<<<GRID, 128>>>(x, c, out, out_size);
}

// round 11
// speedup vs baseline: 1.9504x; 1.2279x over previous
#include <cuda_runtime.h>
#include <cstdint>

#define NN 256
#define KK 64
#define TT 128
#define FF 64
#define TN 8
#define TK 16
#define TC2 4
#define GRID 128

typedef unsigned long long u64;
typedef unsigned int u32;

// ---------------- scratch (no allocations allowed) ----------------
__device__ float g_dist[NN * KK];
__device__ float g_qpart[GRID * KK];
__device__ float g_lossb[GRID];
__device__ int g_c1, g_f1, g_c2, g_f2, g_c3;   // zero-init sync state

__device__ __forceinline__ u64 ffma2(u64 a, u64 b, u64 c) {
    u64 d;
    asm("fma.rn.f32x2 %0, %1, %2, %3;" : "=l"(d) : "l"(a), "l"(b), "l"(c));
    return d;
}
__device__ __forceinline__ float2 upk(u64 v) {
    float2 r;
    asm("mov.b64 {%0, %1}, %2;" : "=f"(r.x), "=f"(r.y) : "l"(v));
    return r;
}
__device__ __forceinline__ float fsqrt_approx(float x) {
    float r;
    asm("sqrt.approx.f32 %0, %1;" : "=f"(r) : "f"(x));
    return r;
}
__device__ __forceinline__ void bar_group(int id) {
    asm volatile("bar.sync %0, 128;" :: "r"(id) : "memory");
}
__device__ __forceinline__ void cp16(u32 s, const float4* g) {
    asm volatile("cp.async.cg.shared.global [%0], [%1], 16;" :: "r"(s), "l"(g));
}
__device__ __forceinline__ void cp_commit_wait() {
    asm volatile("cp.async.commit_group;\ncp.async.wait_group 0;" ::: "memory");
}

// device-wide barrier: all GRID blocks co-resident (128 blocks, 1/SM)
__device__ __forceinline__ void gsync(int* cnt, int* flag) {
    __syncthreads();
    if (threadIdx.x == 0) {
        __threadfence();
        if (atomicAdd(cnt, 1) == GRID - 1) {
            atomicExch(flag, 1);
        } else {
            while (atomicAdd(flag, 0) == 0) { __nanosleep(32); }
        }
    }
    __syncthreads();
}

__global__ void __launch_bounds__(256, 1)
soft_kmeans_mega(const float* __restrict__ x, const float* __restrict__ c,
                 float* __restrict__ out, int out_size) {
    // 48KB: two 24KB group regions in phase 1; aliased for combine/softmax after
    __shared__ float4 smem4[2][1536];      // per group: xs [0,512), cs [512,1536)

    const int tid = threadIdx.x;
    const int b   = blockIdx.x;
    const int g   = tid >> 7;              // warp-group 0/1 (T halves)
    const int wt  = tid & 127;

    // ================= Phase 1: distance tile (8n x 16k), T split =========
    {
        const int fg = wt & 15;            // f-group of 4 floats
        const int pg = wt >> 4;
        const int ni = pg & 1;             // 2 n-subtiles of 4
        const int ki = pg >> 1;            // 4 k-subtiles of 4
        const int n0 = (b >> 2) * TN;
        const int k0 = (b & 3) * TK;

        const float4* __restrict__ xg = (const float4*)x;  // (n*TT+t)*16+f4
        const float4* __restrict__ cg = (const float4*)c;

        const ulonglong2* xsu = (const ulonglong2*)&smem4[g][0];
        const ulonglong2* csu = (const ulonglong2*)&smem4[g][512];
        const u32 xs_s = (u32)__cvta_generic_to_shared(&smem4[g][0]);
        const u32 cs_s = (u32)__cvta_generic_to_shared(&smem4[g][512]);

        u64 acc[4][4][2];
        u64 x2a[4][2], c2a[4][2];
#pragma unroll
        for (int i = 0; i < 4; i++) {
            x2a[i][0] = 0ull; x2a[i][1] = 0ull;
            c2a[i][0] = 0ull; c2a[i][1] = 0ull;
#pragma unroll
            for (int j = 0; j < 4; j++) { acc[i][j][0] = 0ull; acc[i][j][1] = 0ull; }
        }

        for (int ch = 0; ch < 16; ch++) {
            const int t0 = g * 64 + ch * TC2;
            bar_group(1 + g);              // prev compute done, safe to overwrite
            // x tile: 8n*4t*16f4 = 512 float4, 4 per thread
#pragma unroll
            for (int i = 0; i < 4; i++) {
                int idx   = wt + i * 128;
                int nn    = idx >> 6;
                int inner = idx & 63;      // tt*16 + f4
                cp16(xs_s + idx * 16,
                     xg + ((n0 + nn) * TT + t0 + (inner >> 4)) * 16 + (inner & 15));
            }
            // c tile: 16k*4t*16f4 = 1024 float4, 8 per thread
#pragma unroll
            for (int i = 0; i < 8; i++) {
                int idx   = wt + i * 128;
                int kk    = idx >> 6;
                int inner = idx & 63;
                cp16(cs_s + idx * 16,
                     cg + ((k0 + kk) * TT + t0 + (inner >> 4)) * 16 + (inner & 15));
            }
            cp_commit_wait();
            bar_group(1 + g);              // tile visible to whole group

#pragma unroll
            for (int tt = 0; tt < TC2; tt++) {
                ulonglong2 xv[4], cv[4];
#pragma unroll
                for (int i = 0; i < 4; i++)
                    xv[i] = xsu[((ni * 4 + i) * TC2 + tt) * 16 + fg];
#pragma unroll
                for (int j = 0; j < 4; j++)
                    cv[j] = csu[((ki * 4 + j) * TC2 + tt) * 16 + fg];
#pragma unroll
                for (int i = 0; i < 4; i++) {
                    x2a[i][0] = ffma2(xv[i].x, xv[i].x, x2a[i][0]);
                    x2a[i][1] = ffma2(xv[i].y, xv[i].y, x2a[i][1]);
                }
#pragma unroll
                for (int j = 0; j < 4; j++) {
                    c2a[j][0] = ffma2(cv[j].x, cv[j].x, c2a[j][0]);
                    c2a[j][1] = ffma2(cv[j].y, cv[j].y, c2a[j][1]);
                }
#pragma unroll
                for (int i = 0; i < 4; i++)
#pragma unroll
                    for (int j = 0; j < 4; j++) {
                        acc[i][j][0] = ffma2(xv[i].x, cv[j].x, acc[i][j][0]);
                        acc[i][j][1] = ffma2(xv[i].y, cv[j].y, acc[i][j][1]);
                    }
            }
        }

        // -------- unpack into va[96]: acc(64) | x2(16) | c2(16) --------
        float va[96];
#pragma unroll
        for (int i = 0; i < 4; i++)
#pragma unroll
            for (int j = 0; j < 4; j++) {
                float2 a0 = upk(acc[i][j][0]), a1 = upk(acc[i][j][1]);
                int p = (i * 4 + j) * 4;
                va[p] = a0.x; va[p + 1] = a0.y; va[p + 2] = a1.x; va[p + 3] = a1.y;
            }
#pragma unroll
        for (int i = 0; i < 4; i++) {
            float2 a0 = upk(x2a[i][0]), a1 = upk(x2a[i][1]);
            va[64 + i * 4] = a0.x; va[64 + i * 4 + 1] = a0.y;
            va[64 + i * 4 + 2] = a1.x; va[64 + i * 4 + 3] = a1.y;
        }
#pragma unroll
        for (int j = 0; j < 4; j++) {
            float2 a0 = upk(c2a[j][0]), a1 = upk(c2a[j][1]);
            va[80 + j * 4] = a0.x; va[80 + j * 4 + 1] = a0.y;
            va[80 + j * 4 + 2] = a1.x; va[80 + j * 4 + 3] = a1.y;
        }

        // -------- combine group 1 partials into group 0 (conflict-free) ----
        float* sall = (float*)smem4;       // 12288 floats = 96*128, exact fit
        __syncthreads();
        if (g == 1) {
#pragma unroll
            for (int j = 0; j < 96; j++) sall[j * 128 + wt] = va[j];
        }
        __syncthreads();
        if (g == 0) {
#pragma unroll
            for (int j = 0; j < 96; j++) va[j] += sall[j * 128 + wt];

            // epilogue: d2 = max(x2 + c2 - 2*xc, 0); dist = sum_f sqrt(d2)
#pragma unroll
            for (int i = 0; i < 4; i++) {
#pragma unroll
                for (int j = 0; j < 4; j++) {
                    int p = (i * 4 + j) * 4;
                    float d0 = fmaxf(va[64 + i * 4 + 0] + va[80 + j * 4 + 0] - 2.0f * va[p + 0], 0.0f);
                    float d1 = fmaxf(va[64 + i * 4 + 1] + va[80 + j * 4 + 1] - 2.0f * va[p + 1], 0.0f);
                    float d2 = fmaxf(va[64 + i * 4 + 2] + va[80 + j * 4 + 2] - 2.0f * va[p + 2], 0.0f);
                    float d3 = fmaxf(va[64 + i * 4 + 3] + va[80 + j * 4 + 3] - 2.0f * va[p + 3], 0.0f);
                    float part = fsqrt_approx(d0) + fsqrt_approx(d1) +
                                 fsqrt_approx(d2) + fsqrt_approx(d3);
#pragma unroll
                    for (int off = 8; off; off >>= 1)
                        part += __shfl_down_sync(0xffffffffu, part, off, 16);
                    if (fg == 0)
                        g_dist[(n0 + ni * 4 + i) * KK + (k0 + ki * 4 + j)] = part;
                }
            }
        }
    }

    gsync(&g_c1, &g_f1);   // g_dist complete everywhere

    float* s_tmp  = (float*)smem4;         // 256 floats
    float* s_red  = (float*)smem4 + 256;   // 8 floats
    int*   s_last = (int*)((float*)smem4 + 270);

    // ================= Phase 2: q = softmax_k(1/(1+d^2)), rows 2b,2b+1 =====
    const int rloc = (tid >> 6) & 1;
    const int k    = tid & 63;
    const int n    = b * 2 + rloc;
    const int w    = tid >> 5;
    const int lane = tid & 31;
    const bool act = tid < 128;

    float q = 0.0f, e = 0.0f;
    if (act) {
        float d  = g_dist[n * KK + k];
        float q1 = 1.0f / (1.0f + d * d);   // alpha=1 -> exponent 1
        float m = q1;
#pragma unroll
        for (int o = 16; o; o >>= 1) m = fmaxf(m, __shfl_xor_sync(0xffffffffu, m, o));
        if (lane == 0) s_red[w] = m;
        e = q1;                             // stash q1
    }
    __syncthreads();
    if (act) {
        float m = fmaxf(s_red[rloc * 2], s_red[rloc * 2 + 1]);
        e = expf(e - m);
        float s = e;
#pragma unroll
        for (int o = 16; o; o >>= 1) s += __shfl_xor_sync(0xffffffffu, s, o);
        if (lane == 0) s_red[4 + w] = s;
    }
    __syncthreads();
    if (act) {
        float s = s_red[4 + rloc * 2] + s_red[4 + rloc * 2 + 1];
        q = e / s;
        out[n * KK + k] = q;
        s_tmp[tid] = q;
    }
    __syncthreads();
    if (tid < 64) g_qpart[b * KK + tid] = s_tmp[tid] + s_tmp[tid + 64];

    gsync(&g_c2, &g_f2);   // all qpart written

    // ================= Phase 3: qsum, p, loss =================
    {
        // qsum[k] = sum over 128 blocks; 4-way split over thread quarters
        const int quarter = tid >> 6;
        const int kq = tid & 63;
        float part = 0.0f;
#pragma unroll 8
        for (int bb = 0; bb < 32; bb++)
            part += g_qpart[(quarter * 32 + bb) * KK + kq];
        s_tmp[tid] = part;
        __syncthreads();
        float t = 0.0f;
        if (act) {
            float qsum = s_tmp[k] + s_tmp[64 + k] + s_tmp[128 + k] + s_tmp[192 + k];
            t = (q * q) / qsum;
            float m = t;
#pragma unroll
            for (int o = 16; o; o >>= 1) m = fmaxf(m, __shfl_xor_sync(0xffffffffu, m, o));
            if (lane == 0) s_red[w] = m;
        }
        __syncthreads();
        if (act) {
            float m = fmaxf(s_red[rloc * 2], s_red[rloc * 2 + 1]);
            e = expf(t - m);
            float s = e;
#pragma unroll
            for (int o = 16; o; o >>= 1) s += __shfl_xor_sync(0xffffffffu, s, o);
            if (lane == 0) s_red[4 + w] = s;
        }
        __syncthreads();
        if (act) {
            float s = s_red[4 + rloc * 2] + s_red[4 + rloc * 2 + 1];
            float p = e / s;
            float term = q * (logf(q) - p);
#pragma unroll
            for (int o = 16; o; o >>= 1) term += __shfl_xor_sync(0xffffffffu, term, o);
            if (lane == 0) s_red[w] = term;
        }
        __syncthreads();
        if (tid == 0)
            g_lossb[b] = s_red[0] + s_red[1] + s_red[2] + s_red[3];
        __syncthreads();
    }

    // ================= Phase 4: last block finalizes loss, resets sync =====
    if (tid == 0) {
        __threadfence();
        int old = atomicAdd(&g_c3, 1);
        *s_last = (old == GRID - 1) ? 1 : 0;
    }
    __syncthreads();
    if (*s_last) {
        if (tid < 128) s_tmp[tid] = g_lossb[tid];
        __syncthreads();
#pragma unroll
        for (int o = 64; o; o >>= 1) {
            if (tid < o) s_tmp[tid] += s_tmp[tid + o];
            __syncthreads();
        }
        if (tid == 0) {
            if (out_size > NN * KK) out[NN * KK] = s_tmp[0] / (float)NN;
            atomicExch(&g_c1, 0); atomicExch(&g_f1, 0);
            atomicExch(&g_c2, 0); atomicExch(&g_f2, 0);
            atomicExch(&g_c3, 0);
            __threadfence();
        }
    }
}

extern "C" void kernel_launch(void* const* d_in, const int* in_sizes, int n_in,
                              void* d_out, int out_size) {
    const float* x = (const float*)d_in[0];   // inputs  (N,T,F)
    const float* c = (const float*)d_in[1];   // clusters(K,T,F)
    float* out = (float*)d_out;

    soft_kmeans_mega<<<GRID, 256>>>(x, c, out, out_size);
}

// round 12
// speedup vs baseline: 2.1071x; 1.0804x over previous
#include <cuda_runtime.h>
#include <cstdint>

#define NN 256
#define KK 64
#define TT 128
#define FF 64
#define TN 8
#define TK 16
#define TC2 4
#define GRID 128
#define SMEM_BYTES (2 * 2 * 1536 * 16)   // 2 groups x 2 stages x 1536 float4 = 96KB

typedef unsigned long long u64;
typedef unsigned int u32;

// ---------------- scratch (no allocations allowed) ----------------
__device__ float g_dist[NN * KK];
__device__ float g_qpart[GRID * KK];
__device__ float g_lossb[GRID];
__device__ int g_c1, g_f1, g_c2, g_f2, g_c3;   // zero-init sync state

__device__ __forceinline__ u64 ffma2(u64 a, u64 b, u64 c) {
    u64 d;
    asm("fma.rn.f32x2 %0, %1, %2, %3;" : "=l"(d) : "l"(a), "l"(b), "l"(c));
    return d;
}
__device__ __forceinline__ float2 upk(u64 v) {
    float2 r;
    asm("mov.b64 {%0, %1}, %2;" : "=f"(r.x), "=f"(r.y) : "l"(v));
    return r;
}
__device__ __forceinline__ float fsqrt_approx(float x) {
    float r;
    asm("sqrt.approx.f32 %0, %1;" : "=f"(r) : "f"(x));
    return r;
}
__device__ __forceinline__ void bar_group(int id) {
    asm volatile("bar.sync %0, 128;" :: "r"(id) : "memory");
}
__device__ __forceinline__ void cp16(u32 s, const float4* g) {
    asm volatile("cp.async.cg.shared.global [%0], [%1], 16;" :: "r"(s), "l"(g));
}
__device__ __forceinline__ void cp_commit() {
    asm volatile("cp.async.commit_group;" ::: "memory");
}
template <int N>
__device__ __forceinline__ void cp_wait() {
    asm volatile("cp.async.wait_group %0;" :: "n"(N) : "memory");
}

// device-wide barrier: all GRID blocks co-resident (128 blocks, 1/SM)
__device__ __forceinline__ void gsync(int* cnt, int* flag) {
    __syncthreads();
    if (threadIdx.x == 0) {
        __threadfence();
        if (atomicAdd(cnt, 1) == GRID - 1) {
            atomicExch(flag, 1);
        } else {
            while (atomicAdd(flag, 0) == 0) { __nanosleep(32); }
        }
    }
    __syncthreads();
}

extern __shared__ float4 smem4[];   // [group][stage][1536]: xs [0,512), cs [512,1536)

__global__ void __launch_bounds__(256, 1)
soft_kmeans_mega(const float* __restrict__ x, const float* __restrict__ c,
                 float* __restrict__ out, int out_size) {
    const int tid = threadIdx.x;
    const int b   = blockIdx.x;
    const int g   = tid >> 7;              // warp-group 0/1 (T halves)
    const int wt  = tid & 127;

    // ================= Phase 1: distance tile (8n x 16k), T split, 2-stage ==
    {
        const int fg = wt & 15;            // f-group of 4 floats
        const int pg = wt >> 4;
        const int ni = pg & 1;             // 2 n-subtiles of 4
        const int ki = pg >> 1;            // 4 k-subtiles of 4
        const int n0 = (b >> 2) * TN;
        const int k0 = (b & 3) * TK;

        const float4* __restrict__ xg = (const float4*)x;  // (n*TT+t)*16+f4
        const float4* __restrict__ cg = (const float4*)c;

        const u32 base_s = (u32)__cvta_generic_to_shared(smem4);
        const u32 g_s    = base_s + g * 2 * 24576;          // group's 2 stages

        u64 acc[4][4][2];
        u64 x2a[4][2], c2a[4][2];
#pragma unroll
        for (int i = 0; i < 4; i++) {
            x2a[i][0] = 0ull; x2a[i][1] = 0ull;
            c2a[i][0] = 0ull; c2a[i][1] = 0ull;
#pragma unroll
            for (int j = 0; j < 4; j++) { acc[i][j][0] = 0ull; acc[i][j][1] = 0ull; }
        }

        // -------- issue loads for chunk ch into stage st --------
        auto issue_chunk = [&](int ch, int st) {
            const int t0 = g * 64 + ch * TC2;
            const u32 xs_s = g_s + st * 24576;
            const u32 cs_s = xs_s + 512 * 16;
            // x tile: 8n*4t*16f4 = 512 float4, 4 per thread
#pragma unroll
            for (int i = 0; i < 4; i++) {
                int idx   = wt + i * 128;
                int nn    = idx >> 6;
                int inner = idx & 63;      // tt*16 + f4
                cp16(xs_s + idx * 16,
                     xg + ((n0 + nn) * TT + t0 + (inner >> 4)) * 16 + (inner & 15));
            }
            // c tile: 16k*4t*16f4 = 1024 float4, 8 per thread
#pragma unroll
            for (int i = 0; i < 8; i++) {
                int idx   = wt + i * 128;
                int kk    = idx >> 6;
                int inner = idx & 63;
                cp16(cs_s + idx * 16,
                     cg + ((k0 + kk) * TT + t0 + (inner >> 4)) * 16 + (inner & 15));
            }
            cp_commit();
        };

        issue_chunk(0, 0);                  // prologue

#pragma unroll 2
        for (int ch = 0; ch < 16; ch++) {
            const int st = ch & 1;
            bar_group(1 + g);               // compute of ch-1 done -> stage st^1 free
            if (ch < 15) {
                issue_chunk(ch + 1, st ^ 1);
                cp_wait<1>();               // chunk ch landed (only ch+1 may be pending)
            } else {
                cp_wait<0>();
            }
            bar_group(1 + g);               // chunk ch visible group-wide

            const ulonglong2* xsu = (const ulonglong2*)(smem4 + (g * 2 + st) * 1536);
            const ulonglong2* csu = xsu + 512;
#pragma unroll
            for (int tt = 0; tt < TC2; tt++) {
                ulonglong2 xv[4], cv[4];
#pragma unroll
                for (int i = 0; i < 4; i++)
                    xv[i] = xsu[((ni * 4 + i) * TC2 + tt) * 16 + fg];
#pragma unroll
                for (int j = 0; j < 4; j++)
                    cv[j] = csu[((ki * 4 + j) * TC2 + tt) * 16 + fg];
#pragma unroll
                for (int i = 0; i < 4; i++) {
                    x2a[i][0] = ffma2(xv[i].x, xv[i].x, x2a[i][0]);
                    x2a[i][1] = ffma2(xv[i].y, xv[i].y, x2a[i][1]);
                }
#pragma unroll
                for (int j = 0; j < 4; j++) {
                    c2a[j][0] = ffma2(cv[j].x, cv[j].x, c2a[j][0]);
                    c2a[j][1] = ffma2(cv[j].y, cv[j].y, c2a[j][1]);
                }
#pragma unroll
                for (int i = 0; i < 4; i++)
#pragma unroll
                    for (int j = 0; j < 4; j++) {
                        acc[i][j][0] = ffma2(xv[i].x, cv[j].x, acc[i][j][0]);
                        acc[i][j][1] = ffma2(xv[i].y, cv[j].y, acc[i][j][1]);
                    }
            }
        }

        // -------- unpack into va[96]: acc(64) | x2(16) | c2(16) --------
        float va[96];
#pragma unroll
        for (int i = 0; i < 4; i++)
#pragma unroll
            for (int j = 0; j < 4; j++) {
                float2 a0 = upk(acc[i][j][0]), a1 = upk(acc[i][j][1]);
                int p = (i * 4 + j) * 4;
                va[p] = a0.x; va[p + 1] = a0.y; va[p + 2] = a1.x; va[p + 3] = a1.y;
            }
#pragma unroll
        for (int i = 0; i < 4; i++) {
            float2 a0 = upk(x2a[i][0]), a1 = upk(x2a[i][1]);
            va[64 + i * 4] = a0.x; va[64 + i * 4 + 1] = a0.y;
            va[64 + i * 4 + 2] = a1.x; va[64 + i * 4 + 3] = a1.y;
        }
#pragma unroll
        for (int j = 0; j < 4; j++) {
            float2 a0 = upk(c2a[j][0]), a1 = upk(c2a[j][1]);
            va[80 + j * 4] = a0.x; va[80 + j * 4 + 1] = a0.y;
            va[80 + j * 4 + 2] = a1.x; va[80 + j * 4 + 3] = a1.y;
        }

        // -------- combine group 1 partials into group 0 (conflict-free) ----
        float* sall = (float*)smem4;       // 96*128 floats = 48KB (fits)
        __syncthreads();
        if (g == 1) {
#pragma unroll
            for (int j = 0; j < 96; j++) sall[j * 128 + wt] = va[j];
        }
        __syncthreads();
        if (g == 0) {
#pragma unroll
            for (int j = 0; j < 96; j++) va[j] += sall[j * 128 + wt];

            // epilogue: d2 = max(x2 + c2 - 2*xc, 0); dist = sum_f sqrt(d2)
#pragma unroll
            for (int i = 0; i < 4; i++) {
#pragma unroll
                for (int j = 0; j < 4; j++) {
                    int p = (i * 4 + j) * 4;
                    float d0 = fmaxf(va[64 + i * 4 + 0] + va[80 + j * 4 + 0] - 2.0f * va[p + 0], 0.0f);
                    float d1 = fmaxf(va[64 + i * 4 + 1] + va[80 + j * 4 + 1] - 2.0f * va[p + 1], 0.0f);
                    float d2 = fmaxf(va[64 + i * 4 + 2] + va[80 + j * 4 + 2] - 2.0f * va[p + 2], 0.0f);
                    float d3 = fmaxf(va[64 + i * 4 + 3] + va[80 + j * 4 + 3] - 2.0f * va[p + 3], 0.0f);
                    float part = fsqrt_approx(d0) + fsqrt_approx(d1) +
                                 fsqrt_approx(d2) + fsqrt_approx(d3);
#pragma unroll
                    for (int off = 8; off; off >>= 1)
                        part += __shfl_down_sync(0xffffffffu, part, off, 16);
                    if (fg == 0)
                        g_dist[(n0 + ni * 4 + i) * KK + (k0 + ki * 4 + j)] = part;
                }
            }
        }
    }

    gsync(&g_c1, &g_f1);   // g_dist complete everywhere

    float* s_tmp  = (float*)smem4;         // 256 floats
    float* s_red  = (float*)smem4 + 256;   // 8 floats
    int*   s_last = (int*)((float*)smem4 + 270);

    // ================= Phase 2: q = softmax_k(1/(1+d^2)), rows 2b,2b+1 =====
    const int rloc = (tid >> 6) & 1;
    const int k    = tid & 63;
    const int n    = b * 2 + rloc;
    const int w    = tid >> 5;
    const int lane = tid & 31;
    const bool act = tid < 128;

    float q = 0.0f, e = 0.0f;
    if (act) {
        float d  = g_dist[n * KK + k];
        float q1 = 1.0f / (1.0f + d * d);   // alpha=1 -> exponent 1
        float m = q1;
#pragma unroll
        for (int o = 16; o; o >>= 1) m = fmaxf(m, __shfl_xor_sync(0xffffffffu, m, o));
        if (lane == 0) s_red[w] = m;
        e = q1;                             // stash q1
    }
    __syncthreads();
    if (act) {
        float m = fmaxf(s_red[rloc * 2], s_red[rloc * 2 + 1]);
        e = expf(e - m);
        float s = e;
#pragma unroll
        for (int o = 16; o; o >>= 1) s += __shfl_xor_sync(0xffffffffu, s, o);
        if (lane == 0) s_red[4 + w] = s;
    }
    __syncthreads();
    if (act) {
        float s = s_red[4 + rloc * 2] + s_red[4 + rloc * 2 + 1];
        q = e / s;
        out[n * KK + k] = q;
        s_tmp[tid] = q;
    }
    __syncthreads();
    if (tid < 64) g_qpart[b * KK + tid] = s_tmp[tid] + s_tmp[tid + 64];

    gsync(&g_c2, &g_f2);   // all qpart written

    // ================= Phase 3: qsum, p, loss =================
    {
        // qsum[k] = sum over 128 blocks; 4-way split over thread quarters
        const int quarter = tid >> 6;
        const int kq = tid & 63;
        float part = 0.0f;
#pragma unroll 8
        for (int bb = 0; bb < 32; bb++)
            part += g_qpart[(quarter * 32 + bb) * KK + kq];
        s_tmp[tid] = part;
        __syncthreads();
        float t = 0.0f;
        if (act) {
            float qsum = s_tmp[k] + s_tmp[64 + k] + s_tmp[128 + k] + s_tmp[192 + k];
            t = (q * q) / qsum;
            float m = t;
#pragma unroll
            for (int o = 16; o; o >>= 1) m = fmaxf(m, __shfl_xor_sync(0xffffffffu, m, o));
            if (lane == 0) s_red[w] = m;
        }
        __syncthreads();
        if (act) {
            float m = fmaxf(s_red[rloc * 2], s_red[rloc * 2 + 1]);
            e = expf(t - m);
            float s = e;
#pragma unroll
            for (int o = 16; o; o >>= 1) s += __shfl_xor_sync(0xffffffffu, s, o);
            if (lane == 0) s_red[4 + w] = s;
        }
        __syncthreads();
        if (act) {
            float s = s_red[4 + rloc * 2] + s_red[4 + rloc * 2 + 1];
            float p = e / s;
            float term = q * (logf(q) - p);
#pragma unroll
            for (int o = 16; o; o >>= 1) term += __shfl_xor_sync(0xffffffffu, term, o);
            if (lane == 0) s_red[w] = term;
        }
        __syncthreads();
        if (tid == 0)
            g_lossb[b] = s_red[0] + s_red[1] + s_red[2] + s_red[3];
        __syncthreads();
    }

    // ================= Phase 4: last block finalizes loss, resets sync =====
    if (tid == 0) {
        __threadfence();
        int old = atomicAdd(&g_c3, 1);
        *s_last = (old == GRID - 1) ? 1 : 0;
    }
    __syncthreads();
    if (*s_last) {
        if (tid < 128) s_tmp[tid] = g_lossb[tid];
        __syncthreads();
#pragma unroll
        for (int o = 64; o; o >>= 1) {
            if (tid < o) s_tmp[tid] += s_tmp[tid + o];
            __syncthreads();
        }
        if (tid == 0) {
            if (out_size > NN * KK) out[NN * KK] = s_tmp[0] / (float)NN;
            atomicExch(&g_c1, 0); atomicExch(&g_f1, 0);
            atomicExch(&g_c2, 0); atomicExch(&g_f2, 0);
            atomicExch(&g_c3, 0);
            __threadfence();
        }
    }
}

extern "C" void kernel_launch(void* const* d_in, const int* in_sizes, int n_in,
                              void* d_out, int out_size) {
    const float* x = (const float*)d_in[0];   // inputs  (N,T,F)
    const float* c = (const float*)d_in[1];   // clusters(K,T,F)
    float* out = (float*)d_out;

    cudaFuncSetAttribute(soft_kmeans_mega,
                         cudaFuncAttributeMaxDynamicSharedMemorySize, SMEM_BYTES);
    soft_kmeans_mega<<<GRID, 256, SMEM_BYTES>>>(x, c, out, out_size);
}